// round 7
// baseline (speedup 1.0000x reference)
#include <cuda_runtime.h>
#include <math.h>

#define B_   128
#define T_   512
#define NI   64
#define NH   1024
#define NO   64

#define NJT    33            // 32 rec/fgt j-tiles + 1 dec j-tile
#define KSPLIT 4
#define NCTA   (NJT*KSPLIT)  // 132  -> exactly 1 CTA/SM (148 SMs)
#define NTHR   256
#define KSL    256           // k-slice per CTA
#define BK     16
#define NCHUNK (KSL/BK)      // 16
#define JP_CTA 32            // column-pairs per CTA
#define OUTS_CTA 4096        // 128 b * 32 pairs
#define SMEM_BYTES (KSL*JP_CTA*8 + 2*BK*B_*4)   // 64KB ws + 16KB hs = 80KB

// ---------------- scratch ------------------------------------------------------
__device__ float g_enc[(size_t)T_ * B_ * NH];          // [t][b][h]
__device__ float g_hidB[2][B_ * NH];                   // [b][h]
__device__ float g_hidT[2][NH * B_];                   // [h][b]
__device__ unsigned long long g_part[(size_t)NCTA * OUTS_CTA]; // [jt*4+ks][b*32+jp]
__device__ unsigned g_flag[NJT];
__device__ volatile unsigned g_gen;
__device__ unsigned g_cnt;

// ---------------- helpers ------------------------------------------------------
#define FMA2(d, a, b) asm("fma.rn.f32x2 %0, %1, %2, %0;" : "+l"(d) : "l"(a), "l"(b))
__device__ __forceinline__ unsigned long long dup2(float h) {
    unsigned long long r;
    asm("mov.b64 %0, {%1, %1};" : "=l"(r) : "f"(h));
    return r;
}

__device__ __forceinline__ void grid_barrier() {
    __threadfence();
    __syncthreads();
    if (threadIdx.x == 0) {
        unsigned gen = g_gen;
        if (atomicAdd(&g_cnt, 1) == NCTA - 1) {
            g_cnt = 0;
            __threadfence();
            g_gen = gen + 1;
        } else {
            while (g_gen == gen) __nanosleep(32);
        }
        __threadfence();
    }
    __syncthreads();
}

// ---------------- reset + init --------------------------------------------------
__global__ void reset_kernel() {
    int i = threadIdx.x;
    if (i == 0) { g_gen = 0; g_cnt = 0; }
    if (i < NJT) g_flag[i] = 0;
}

__global__ void init_hidden_kernel(const float* __restrict__ hinit_w,
                                   const float* __restrict__ hinit_b) {
    int idx = blockIdx.x * blockDim.x + threadIdx.x;
    if (idx < B_ * NH) {
        int hT = idx >> 7;                 // [h][b]
        g_hidT[0][idx] = hinit_w[hT] + hinit_b[hT];
        int hB = idx & (NH - 1);           // [b][h]
        g_hidB[0][idx] = hinit_w[hB] + hinit_b[hB];
    }
}

// ---------------- encoder GEMM (one-shot) ---------------------------------------
__global__ void __launch_bounds__(256) enc_kernel(const float* __restrict__ x,
                                                  const float* __restrict__ enc_w,
                                                  const float* __restrict__ enc_b) {
    __shared__ float xs[32][NI + 1];
    __shared__ float ws[64][NI + 1];
    const int tid = threadIdx.x;
    const int tb0 = blockIdx.x * 32;
    const int h0  = blockIdx.y * 64;

    for (int i = tid; i < 32 * NI; i += 256) {
        int r = i >> 6, c = i & 63;
        int tb = tb0 + r;
        int t = tb >> 7, b = tb & 127;
        xs[r][c] = x[(size_t)b * (T_ * NI) + t * NI + c];
    }
    for (int i = tid; i < 64 * NI; i += 256) {
        int r = i >> 6, c = i & 63;
        ws[r][c] = enc_w[(h0 + r) * NI + c];
    }
    __syncthreads();

    const int rg = tid & 7;
    const int hg = tid >> 3;
    float acc[4][2] = {};
#pragma unroll
    for (int k = 0; k < NI; k++) {
        float w0 = ws[hg * 2 + 0][k];
        float w1 = ws[hg * 2 + 1][k];
#pragma unroll
        for (int j = 0; j < 4; j++) {
            float xv = xs[rg * 4 + j][k];
            acc[j][0] += xv * w0;
            acc[j][1] += xv * w1;
        }
    }
#pragma unroll
    for (int j = 0; j < 4; j++) {
        int tb = tb0 + rg * 4 + j;
#pragma unroll
        for (int q = 0; q < 2; q++) {
            int h = h0 + hg * 2 + q;
            g_enc[(size_t)tb * NH + h] = acc[j][q] + enc_b[h];
        }
    }
}

// ---------------- persistent recurrent kernel ------------------------------------
// CTA: jt = bid>>2 (j-tile of 32 pairs), ks = bid&3 (k-slot of 256).
// Pair p = jt*32+jp: p<1024 -> (rec_w[p,:], fgt_w[p,:]); p>=1024 -> dec cols (2m,2m+1), m=p-1024.
__global__ void __launch_bounds__(NTHR) persist_kernel(const float* __restrict__ rec_w,
                                                       const float* __restrict__ fgt_w,
                                                       const float* __restrict__ dec_w,
                                                       const float* __restrict__ dec_b,
                                                       float* __restrict__ out,
                                                       int writeHidden) {
    extern __shared__ __align__(16) char smem[];
    unsigned long long* ws = (unsigned long long*)smem;     // [256 k][32 jp] (wA,wB)
    float* hsf = (float*)(smem + KSL * JP_CTA * 8);         // [2][16 k][128 b]

    const int tid = threadIdx.x;
    const int bid = blockIdx.x;
    const int jt  = bid >> 2;        // 0..32
    const int ks  = bid & 3;         // 0..3
    const int j0  = jt * JP_CTA;
    const int kbase = ks * KSL;

    const int jg = tid & 7;          // 8 j-groups of 4 pairs
    const int bg = tid >> 3;         // 32 b-groups of 4 rows

    // ---- weights -> SMEM once ----
    for (int i = tid; i < KSL * JP_CTA; i += NTHR) {
        int k = i & (KSL - 1), jp = i >> 8;
        int p = j0 + jp;
        int gk = kbase + k;
        float a, b;
        if (p < 1024) { a = rec_w[p * NH + gk]; b = fgt_w[p * NH + gk]; }
        else { int m = p - 1024; a = dec_w[(2 * m) * NH + gk]; b = dec_w[(2 * m + 1) * NH + gk]; }
        ws[k * JP_CTA + jp] = ((unsigned long long)__float_as_uint(b) << 32) | __float_as_uint(a);
    }
    __syncthreads();

    // combine-phase identities: 4 CTAs of a jt cover 128 b; each thread: 1 b x 4 jp
    const int bloc = ks * 32 + (tid >> 3);
    const int jpb  = (tid & 7) * 4;
    float4 db0 = make_float4(0, 0, 0, 0), db1 = db0;
    if (jt == 32) {
        db0 = *(const float4*)(dec_b + jpb * 2);
        db1 = *(const float4*)(dec_b + jpb * 2 + 4);
    }

    unsigned long long* mypart = g_part + (size_t)bid * OUTS_CTA;

    for (int t = 0; t <= T_; t++) {
        const int cur = t & 1, nxt = (t + 1) & 1;
        const bool work = (t < T_) || (jt == 32);

        if (work) {
            // ================= GEMM over K-slice =================
            const float* __restrict__ hsrc = g_hidT[cur] + kbase * B_;
            float4 pf[2];
#pragma unroll
            for (int i = 0; i < 2; i++) {
                int slot = i * NTHR + tid;
                int row = slot >> 5, c4 = slot & 31;
                pf[i] = __ldcg((const float4*)(hsrc + row * B_ + c4 * 4));
            }
#pragma unroll
            for (int i = 0; i < 2; i++) {
                int slot = i * NTHR + tid;
                int row = slot >> 5, c4 = slot & 31;
                *(float4*)(hsf + row * B_ + c4 * 4) = pf[i];
            }

            ulonglong2 acc[4][2];
#pragma unroll
            for (int ib = 0; ib < 4; ib++)
#pragma unroll
                for (int jj = 0; jj < 2; jj++) { acc[ib][jj].x = 0ull; acc[ib][jj].y = 0ull; }

            for (int kc = 0; kc < NCHUNK; kc++) {
                if (kc + 1 < NCHUNK) {
#pragma unroll
                    for (int i = 0; i < 2; i++) {
                        int slot = i * NTHR + tid;
                        int row = slot >> 5, c4 = slot & 31;
                        pf[i] = __ldcg((const float4*)(hsrc + ((kc + 1) * BK + row) * B_ + c4 * 4));
                    }
                }
                __syncthreads();
                if (kc + 1 < NCHUNK) {
                    float* hb = hsf + ((kc + 1) & 1) * (BK * B_);
#pragma unroll
                    for (int i = 0; i < 2; i++) {
                        int slot = i * NTHR + tid;
                        int row = slot >> 5, c4 = slot & 31;
                        *(float4*)(hb + row * B_ + c4 * 4) = pf[i];
                    }
                }
                const float* hb = hsf + (kc & 1) * (BK * B_);
#pragma unroll
                for (int kk = 0; kk < BK; kk++) {
                    float4 h0 = *(const float4*)(hb + kk * B_ + bg * 4);
                    const ulonglong2* wr = (const ulonglong2*)(ws + (kc * BK + kk) * JP_CTA + jg * 4);
                    ulonglong2 w0 = wr[0];
                    ulonglong2 w1 = wr[1];
                    unsigned long long d0 = dup2(h0.x), d1 = dup2(h0.y), d2 = dup2(h0.z), d3 = dup2(h0.w);
                    FMA2(acc[0][0].x, d0, w0.x); FMA2(acc[0][0].y, d0, w0.y); FMA2(acc[0][1].x, d0, w1.x); FMA2(acc[0][1].y, d0, w1.y);
                    FMA2(acc[1][0].x, d1, w0.x); FMA2(acc[1][0].y, d1, w0.y); FMA2(acc[1][1].x, d1, w1.x); FMA2(acc[1][1].y, d1, w1.y);
                    FMA2(acc[2][0].x, d2, w0.x); FMA2(acc[2][0].y, d2, w0.y); FMA2(acc[2][1].x, d2, w1.x); FMA2(acc[2][1].y, d2, w1.y);
                    FMA2(acc[3][0].x, d3, w0.x); FMA2(acc[3][0].y, d3, w0.y); FMA2(acc[3][1].x, d3, w1.x); FMA2(acc[3][1].y, d3, w1.y);
                }
            }

            // ---- publish partials: [b][jp] as ulonglong2 (coalesced) ----
#pragma unroll
            for (int ib = 0; ib < 4; ib++) {
                int b = bg * 4 + ib;
#pragma unroll
                for (int jj = 0; jj < 2; jj++)
                    *(ulonglong2*)(mypart + b * JP_CTA + jg * 4 + jj * 2) = acc[ib][jj];
            }
            __threadfence();
            __syncthreads();
            if (tid == 0) {
                atomicAdd(&g_flag[jt], 1u);
                unsigned target = (unsigned)KSPLIT * (unsigned)(t + 1);
                while (((volatile unsigned*)g_flag)[jt] < target) __nanosleep(32);
                __threadfence();
            }
            __syncthreads();

            // ---- combine 4 k-slots + fused epilogue ----
            float R[4] = {0, 0, 0, 0}, F[4] = {0, 0, 0, 0};
            const unsigned long long* gp = g_part + (size_t)(jt * KSPLIT) * OUTS_CTA + bloc * JP_CTA + jpb;
#pragma unroll
            for (int k2 = 0; k2 < KSPLIT; k2++) {
                uint4 q0 = __ldcg((const uint4*)(gp + (size_t)k2 * OUTS_CTA));
                uint4 q1 = __ldcg((const uint4*)(gp + (size_t)k2 * OUTS_CTA + 2));
                R[0] += __uint_as_float(q0.x); F[0] += __uint_as_float(q0.y);
                R[1] += __uint_as_float(q0.z); F[1] += __uint_as_float(q0.w);
                R[2] += __uint_as_float(q1.x); F[2] += __uint_as_float(q1.y);
                R[3] += __uint_as_float(q1.z); F[3] += __uint_as_float(q1.w);
            }

            if (jt < 32) {
                int hg0 = j0 + jpb;
                float4 e  = __ldcg((const float4*)(g_enc + (size_t)t * (B_ * NH) + bloc * NH + hg0));
                float4 ho = __ldcg((const float4*)(g_hidB[cur] + bloc * NH + hg0));
                float hv[4];
                const float ev[4] = {e.x, e.y, e.z, e.w};
                const float hov[4] = {ho.x, ho.y, ho.z, ho.w};
#pragma unroll
                for (int i = 0; i < 4; i++) {
                    float f = 1.0f / (1.0f + __expf(-F[i]));
                    float s = ev[i] + R[i];
                    float hn = s / (1.0f + fabsf(s));
                    hv[i] = (1.0f - f) * hov[i] + f * hn;
                }
                *(float4*)(g_hidB[nxt] + bloc * NH + hg0) = make_float4(hv[0], hv[1], hv[2], hv[3]);
#pragma unroll
                for (int i = 0; i < 4; i++)
                    g_hidT[nxt][(hg0 + i) * B_ + bloc] = hv[i];
            } else if (t >= 1) {
                float4 v0 = make_float4(R[0] + db0.x, F[0] + db0.y, R[1] + db0.z, F[1] + db0.w);
                float4 v1 = make_float4(R[2] + db1.x, F[2] + db1.y, R[3] + db1.z, F[3] + db1.w);
                float* op = out + (size_t)(t - 1) * (B_ * NO) + bloc * NO + jpb * 2;
                *(float4*)op = v0;
                *(float4*)(op + 4) = v1;
            }
        }

        if (t == T_) break;
        grid_barrier();
    }

    // final hidden copy (after out[T-1] has been written by dec CTAs)
    if (writeHidden && jt < 32) {
        int rid = jt * 4 + ks;               // 0..127, each copies 1024 floats
        const float* src = g_hidB[0] + rid * 1024;
        float* dst = out + (size_t)T_ * B_ * NO + rid * 1024;
        *(float4*)(dst + tid * 4) = __ldcg((const float4*)(src + tid * 4));
    }
}

// --------------------------------------------------------------------------------
extern "C" void kernel_launch(void* const* d_in, const int* in_sizes, int n_in,
                              void* d_out, int out_size) {
    const float* x       = (const float*)d_in[0];
    const float* enc_w   = (const float*)d_in[1];
    const float* enc_b   = (const float*)d_in[2];
    const float* rec_w   = (const float*)d_in[3];
    const float* fgt_w   = (const float*)d_in[4];
    const float* dec_w   = (const float*)d_in[5];
    const float* dec_b   = (const float*)d_in[6];
    const float* hinit_w = (const float*)d_in[7];
    const float* hinit_b = (const float*)d_in[8];
    float* out = (float*)d_out;

    reset_kernel<<<1, 64>>>();
    init_hidden_kernel<<<(B_ * NH + 255) / 256, 256>>>(hinit_w, hinit_b);

    dim3 eg(T_ * B_ / 32, NH / 64);
    enc_kernel<<<eg, 256>>>(x, enc_w, enc_b);

    cudaFuncSetAttribute(persist_kernel, cudaFuncAttributeMaxDynamicSharedMemorySize,
                         SMEM_BYTES);
    int writeHidden = (out_size >= T_ * B_ * NO + B_ * NH) ? 1 : 0;
    persist_kernel<<<NCTA, NTHR, SMEM_BYTES>>>(rec_w, fgt_w, dec_w, dec_b, out, writeHidden);
}